// round 17
// baseline (speedup 1.0000x reference)
#include <cuda_runtime.h>
#include <cuda_bf16.h>
#include <cstdint>

#define VOCAB 256
#define CHARS 20
#define ROWS_PER_TILE 32
#define THREADS 256
#define NBUF 3
#define HIST_FLOATS (ROWS_PER_TILE * VOCAB)          // 8192
#define HIST_BYTES  (HIST_FLOATS * 4)                // 32768
#define TASKS       (ROWS_PER_TILE * CHARS)          // 640
#define VEC_THREADS (TASKS / 4)                      // 160 int4 loads
#define GRID_BLOCKS 296                              // 2 resident * 148 SMs

__device__ __forceinline__ uint32_t smem_u32(const void* p) {
    uint32_t a;
    asm("{ .reg .u64 t; cvta.to.shared.u64 t, %1; cvt.u32.u64 %0, t; }"
        : "=r"(a) : "l"(p));
    return a;
}

__device__ __forceinline__ int4 ldg4_pol(const int4* p, uint64_t pol) {
    int4 v;
    asm("ld.global.nc.L2::cache_hint.v4.b32 {%0,%1,%2,%3}, [%4], %5;"
        : "=r"(v.x), "=r"(v.y), "=r"(v.z), "=r"(v.w) : "l"(p), "l"(pol));
    return v;
}

__global__ void __launch_bounds__(THREADS) fofe_pipe3x32_kernel(
    const int* __restrict__ char_ids,
    const float* __restrict__ forgetting_factor,
    float* __restrict__ out,
    int n_tiles)
{
    __shared__ __align__(128) float hist[NBUF][HIST_FLOATS];
    __shared__ float pw_s[CHARS];

    const int t = threadIdx.x;

    // Best-measured residency policy (R7): 9/16 output protected via
    // evict_last, 7/16 sacrificial evict_first stream, ids pinned.
    uint64_t pol_last, pol_first;
    asm("createpolicy.fractional.L2::evict_last.b64 %0, 1.0;"  : "=l"(pol_last));
    asm("createpolicy.fractional.L2::evict_first.b64 %0, 1.0;" : "=l"(pol_first));

    if (t < CHARS) {
        const float alpha = __ldg(forgetting_factor);
        float p = 1.f;
        const int e = (CHARS - 1) - t;
        for (int i = 0; i < e; ++i) p *= alpha;
        pw_s[t] = p;
    }

    // Vectorized task mapping: thread t < 160 owns tasks 4t..4t+3, all in
    // the SAME row (20 % 4 == 0): row = t/5, chars k0..k0+3.
    const bool active = t < VEC_THREADS;
    const int  row  = t / 5;
    const int  slot = row * VOCAB;
    const int  k0   = (4 * t) % CHARS;

    // One-time full zero of all buffers; afterwards sparse re-zero by
    // induction (only previously-touched slots are ever nonzero).
    {
        float4* hz = reinterpret_cast<float4*>(hist);
        const float4 z = make_float4(0.f, 0.f, 0.f, 0.f);
#pragma unroll
        for (int i = 0; i < (NBUF * HIST_FLOATS / 4) / THREADS; ++i)
            hz[t + i * THREADS] = z;
    }

    int tile = blockIdx.x;

    // Per-buffer current ids and touched-slot history (previous use).
    int4 id[NBUF], zp[NBUF];
#pragma unroll
    for (int b = 0; b < NBUF; ++b) {
        id[b] = make_int4(0, 0, 0, 0);
        zp[b] = make_int4(0, 0, 0, 0);
    }

    if (active && tile < n_tiles) {
        const int4* base = reinterpret_cast<const int4*>(
            char_ids + (size_t)tile * TASKS);
        id[0] = ldg4_pol(base + t, pol_last);
    }

    __syncthreads();   // pw_s + zeroed buffers ready
    float pw0 = 0.f, pw1 = 0.f, pw2 = 0.f, pw3 = 0.f;
    if (active) {
        pw0 = pw_s[k0]; pw1 = pw_s[k0 + 1];
        pw2 = pw_s[k0 + 2]; pw3 = pw_s[k0 + 3];
    }

    int buf = 0;
    while (tile < n_tiles) {
        float* h = hist[buf];

        // Buffer reuse gate: up to NBUF-1 bulk groups pending; the group
        // using this buffer was committed NBUF-1 iterations ago.
        if (t == 0)
            asm volatile("cp.async.bulk.wait_group.read %0;" :: "n"(NBUF - 1)
                         : "memory");
        __syncthreads();

        // Sparse re-zero of the slots touched last time this buffer was used
        if (active) {
            h[slot + zp[buf].x] = 0.f; h[slot + zp[buf].y] = 0.f;
            h[slot + zp[buf].z] = 0.f; h[slot + zp[buf].w] = 0.f;
        }
        __syncthreads();

        // Scatter this tile (spread smem atomics)
        if (active) {
            atomicAdd(&h[slot + id[buf].x], pw0);
            atomicAdd(&h[slot + id[buf].y], pw1);
            atomicAdd(&h[slot + id[buf].z], pw2);
            atomicAdd(&h[slot + id[buf].w], pw3);
            zp[buf] = id[buf];
        }

        // Prefetch next tile's ids into the next buffer's registers
        const int nt = tile + GRID_BLOCKS;
        const int nbuf = (buf + 1 == NBUF) ? 0 : buf + 1;
        if (active && nt < n_tiles) {
            const int4* base = reinterpret_cast<const int4*>(
                char_ids + (size_t)nt * TASKS);
            id[nbuf] = ldg4_pol(base + t, pol_last);
        }
        __syncthreads();

        // Bulk TMA store smem -> global with per-tile L2 residency policy
        if (t == 0) {
            asm volatile("fence.proxy.async.shared::cta;" ::: "memory");
            const uint32_t src = smem_u32(h);
            float* dst = out + (size_t)tile * HIST_FLOATS;
            const uint64_t pol = ((tile & 15) < 9) ? pol_last : pol_first;
            asm volatile(
                "cp.async.bulk.global.shared::cta.bulk_group.L2::cache_hint"
                " [%0], [%1], %2, %3;"
                :: "l"(dst), "r"(src), "n"(HIST_BYTES), "l"(pol) : "memory");
            asm volatile("cp.async.bulk.commit_group;" ::: "memory");
        }

        tile = nt;
        buf = nbuf;
    }

    // Drain all outstanding bulk stores before exit
    if (t == 0)
        asm volatile("cp.async.bulk.wait_group 0;" ::: "memory");
}

extern "C" void kernel_launch(void* const* d_in, const int* in_sizes, int n_in,
                              void* d_out, int out_size) {
    const int* char_ids;
    const float* ff;
    if (in_sizes[0] > in_sizes[1]) {
        char_ids = (const int*)d_in[0];
        ff = (const float*)d_in[1];
    } else {
        char_ids = (const int*)d_in[1];
        ff = (const float*)d_in[0];
    }
    float* out = (float*)d_out;

    const int n_rows  = out_size / VOCAB;              // 131072
    const int n_tiles = n_rows / ROWS_PER_TILE;        // 4096

    fofe_pipe3x32_kernel<<<GRID_BLOCKS, THREADS>>>(char_ids, ff, out, n_tiles);
}